// round 14
// baseline (speedup 1.0000x reference)
#include <cuda_runtime.h>
#include <cuda_fp16.h>
#include <math.h>

#define TT 4096
#define HH 1536
#define II 768
#define EE 64
#define KK 8
#define CC 1024

// Scratch (no allocation allowed).
__device__ int    g_cnt[EE];
__device__ int    g_rowtok[EE * CC];
__device__ int    g_te[TT * KK];
__device__ int    g_tpos[TT * KK];
__device__ float  g_tw[TT * KK];
__device__ __half g_xh[(size_t)TT * HH];            // fp16 hidden_states
__device__ __half g_h[(size_t)EE * CC * II];        // SwiGLU activations fp16
__device__ __half g_y[(size_t)EE * CC * HH];        // expert outputs fp16
__device__ __half g_wgh[(size_t)EE * II * HH];      // fp16 w_gate
__device__ __half g_wuh[(size_t)EE * II * HH];      // fp16 w_up
__device__ __half g_wdh[(size_t)EE * HH * II];      // fp16 w_down

// ---------------------------------------------------------------------------
// helpers
// ---------------------------------------------------------------------------
__device__ __forceinline__ void mma16(float* c, const unsigned* a, unsigned b0, unsigned b1) {
    asm volatile(
        "mma.sync.aligned.m16n8k16.row.col.f32.f16.f16.f32 "
        "{%0,%1,%2,%3}, {%4,%5,%6,%7}, {%8,%9}, {%0,%1,%2,%3};\n"
        : "+f"(c[0]), "+f"(c[1]), "+f"(c[2]), "+f"(c[3])
        : "r"(a[0]), "r"(a[1]), "r"(a[2]), "r"(a[3]), "r"(b0), "r"(b1));
}
__device__ __forceinline__ void ldsm4(unsigned* r, unsigned addr) {
    asm volatile("ldmatrix.sync.aligned.m8n8.x4.shared.b16 {%0,%1,%2,%3}, [%4];"
                 : "=r"(r[0]), "=r"(r[1]), "=r"(r[2]), "=r"(r[3]) : "r"(addr));
}
__device__ __forceinline__ void cpa(unsigned dst, const void* src, unsigned sz) {
    asm volatile("cp.async.cg.shared.global [%0], [%1], 16, %2;\n"
                 :: "r"(dst), "l"(src), "r"(sz));
}
#define CP_COMMIT asm volatile("cp.async.commit_group;\n")
#define CP_WAIT1  asm volatile("cp.async.wait_group 1;\n")

__device__ __forceinline__ void conv8(const float4* __restrict__ src, uint4* __restrict__ dst,
                                      size_t i) {
    float4 v0 = src[2 * i], v1 = src[2 * i + 1];
    __half2 h0 = __floats2half2_rn(v0.x, v0.y);
    __half2 h1 = __floats2half2_rn(v0.z, v0.w);
    __half2 h2 = __floats2half2_rn(v1.x, v1.y);
    __half2 h3 = __floats2half2_rn(v1.z, v1.w);
    uint4 o;
    o.x = *(unsigned*)&h0; o.y = *(unsigned*)&h1;
    o.z = *(unsigned*)&h2; o.w = *(unsigned*)&h3;
    dst[i] = o;
}

// ---------------------------------------------------------------------------
// K1: fused [logits + in-block top-8 + dispatch (blocks 0..63)] +
// [fp16 conversion of x, w_gate, w_up (blocks 64..)] + cnt zeroing.
// ---------------------------------------------------------------------------
#define NC1 1536

__global__ __launch_bounds__(256) void k1_kernel(
    const float* __restrict__ x,
    const float* __restrict__ gw,
    const float4* __restrict__ wg32,
    const float4* __restrict__ wu32,
    const float* __restrict__ bias)
{
    int bx  = blockIdx.x;
    int tid = threadIdx.x;

    if (bx >= 64) {
        const size_t XCH = (size_t)TT * HH / 8;
        const size_t WCH = (size_t)EE * II * HH / 8;
        const size_t total = XCH + 2 * WCH;
        size_t idx = (size_t)(bx - 64) * 256 + tid;
        for (size_t i = idx; i < total; i += (size_t)NC1 * 256) {
            if (i < XCH)            conv8((const float4*)x, (uint4*)g_xh, i);
            else if (i < XCH + WCH) conv8(wg32, (uint4*)g_wgh, i - XCH);
            else                    conv8(wu32, (uint4*)g_wuh, i - XCH - WCH);
        }
        return;
    }

    __shared__ float As[16][64];
    __shared__ float Bs[16][64];
    __shared__ float s_sc[64][64];    // sigmoid scores [token][expert]
    __shared__ float s_sel[64][64];   // score + bias for selection

    int tok0 = bx * 64;
    int lrow = tid >> 2;
    int lkq  = (tid & 3) << 2;
    const float* ap = x  + (size_t)(tok0 + lrow) * HH + lkq;
    const float* bp = gw + (size_t)lrow * HH + lkq;
    int tx = (tid & 15) << 2;
    int ty = (tid >> 4) << 2;
    float acc[4][4] = {};

    for (int k0 = 0; k0 < HH; k0 += 16) {
        float4 av = *(const float4*)(ap + k0);
        float4 bv = *(const float4*)(bp + k0);
        __syncthreads();
        As[lkq][lrow] = av.x; As[lkq + 1][lrow] = av.y; As[lkq + 2][lrow] = av.z; As[lkq + 3][lrow] = av.w;
        Bs[lkq][lrow] = bv.x; Bs[lkq + 1][lrow] = bv.y; Bs[lkq + 2][lrow] = bv.z; Bs[lkq + 3][lrow] = bv.w;
        __syncthreads();
        #pragma unroll
        for (int k = 0; k < 16; k++) {
            float4 a = *(const float4*)&As[k][ty];
            float4 b = *(const float4*)&Bs[k][tx];
            float aa[4] = {a.x, a.y, a.z, a.w};
            float bb[4] = {b.x, b.y, b.z, b.w};
            #pragma unroll
            for (int i = 0; i < 4; i++)
                #pragma unroll
                for (int j = 0; j < 4; j++)
                    acc[i][j] = fmaf(aa[i], bb[j], acc[i][j]);
        }
    }
    #pragma unroll
    for (int i = 0; i < 4; i++)
        #pragma unroll
        for (int j = 0; j < 4; j++) {
            float sc = 1.f / (1.f + expf(-acc[i][j]));
            s_sc[ty + i][tx + j]  = sc;
            s_sel[ty + i][tx + j] = sc + bias[tx + j];
        }
    __syncthreads();

    // top-8 + dispatch: 8 warps, each handles 8 tokens
    int warp = tid >> 5, lane = tid & 31;
    for (int tt = warp; tt < 64; tt += 8) {
        int tok = tok0 + tt;
        float sc0 = s_sc[tt][lane];
        float sc1 = s_sc[tt][lane + 32];
        float v0  = s_sel[tt][lane];
        float v1  = s_sel[tt][lane + 32];

        int   my_e = -1;
        float wsum = 0.f;
        #pragma unroll
        for (int k = 0; k < KK; k++) {
            float v; int id;
            if (v0 >= v1) { v = v0; id = lane; } else { v = v1; id = lane + 32; }
            #pragma unroll
            for (int off = 16; off; off >>= 1) {
                float ov = __shfl_xor_sync(0xffffffffu, v, off);
                int   oi = __shfl_xor_sync(0xffffffffu, id, off);
                if (ov > v || (ov == v && oi < id)) { v = ov; id = oi; }
            }
            float s0 = __shfl_sync(0xffffffffu, sc0, id & 31);
            float s1 = __shfl_sync(0xffffffffu, sc1, id & 31);
            wsum += (id < 32) ? s0 : s1;
            if (k == lane) my_e = id;
            if (id == lane)      v0 = -1e30f;
            if (id == lane + 32) v1 = -1e30f;
        }
        {
            int src = (my_e >= 0) ? (my_e & 31) : 0;
            float s0 = __shfl_sync(0xffffffffu, sc0, src);
            float s1 = __shfl_sync(0xffffffffu, sc1, src);
            if (lane < KK) {
                float wgt = ((my_e < 32) ? s0 : s1) / wsum;
                int pos = atomicAdd(&g_cnt[my_e], 1);
                if (pos < CC) g_rowtok[my_e * CC + pos] = tok;
                g_te[tok * KK + lane]   = my_e;
                g_tpos[tok * KK + lane] = pos;
                g_tw[tok * KK + lane]   = wgt;
            }
        }
    }
}

__global__ void zero_cnt_kernel() {
    if (threadIdx.x < EE) g_cnt[threadIdx.x] = 0;
}

// ---------------------------------------------------------------------------
// GEMM kernels (R10 exact): 256 threads, 8 warps, 2 CTAs/SM. BK=32, 3-stage
// cp.async ring, stage = 20 KB.
// gemm1: BM=128, BN=64 per kind (gate+up), warps 4m x 2n, warp 32 x 32/kind.
// gemm2: BM=128, BN=128, warps 4m x 2n, warp 32 x 64.
// ---------------------------------------------------------------------------
#define G_AB    (128 * 80)
#define G_BB    (128 * 80)
#define G_STG   (G_AB + G_BB)              // 20480 per stage
#define NCD     384

__global__ __launch_bounds__(256, 2) void gemm1_kernel(const float4* __restrict__ wd32)
{
    extern __shared__ char smem[];
    int e   = blockIdx.z;
    int tid = threadIdx.x;

    if (e >= EE) {
        int rank = (e - EE) * 96 + blockIdx.y * 12 + blockIdx.x;
        const size_t WCH = (size_t)EE * HH * II / 8;
        for (size_t i = (size_t)rank * 256 + tid; i < WCH; i += (size_t)NCD * 256)
            conv8(wd32, (uint4*)g_wdh, i);
        return;
    }

    int cnt = min(g_cnt[e], CC);
    int m0  = blockIdx.y * 128;
    if (m0 >= cnt) return;
    int n0  = blockIdx.x * 64;

    unsigned sbase = (unsigned)__cvta_generic_to_shared(smem);

    const __half* aptr[2]; unsigned asz[2]; unsigned aoff[2];
    #pragma unroll
    for (int i = 0; i < 2; i++) {
        int c = tid + i * 256;
        int r = c >> 2, ck = c & 3;
        int m = m0 + r;
        int ok = m < cnt;
        int tok = ok ? g_rowtok[e * CC + m] : 0;
        aptr[i] = g_xh + (size_t)tok * HH + ck * 8;
        asz[i]  = ok ? 16u : 0u;
        aoff[i] = (unsigned)(r * 80 + ck * 16);
    }
    const __half* bptr[2]; unsigned boff[2];
    #pragma unroll
    for (int i = 0; i < 2; i++) {
        int c = tid + i * 256;
        int r = c >> 2, ck = c & 3;
        const __half* base = (r < 64)
            ? g_wgh + ((size_t)e * II + n0 + r) * HH
            : g_wuh + ((size_t)e * II + n0 + (r - 64)) * HH;
        bptr[i] = base + ck * 8;
        boff[i] = (unsigned)(G_AB + r * 80 + ck * 16);
    }

    int warp = tid >> 5, lane = tid & 31;
    int wm = (warp & 3) * 32, wn = (warp >> 2) * 32;
    int gq = lane >> 2, t = lane & 3;

    unsigned a_lane = (unsigned)((lane & 15) * 80 + (lane >> 4) * 16);
    unsigned b_lane = (unsigned)(((lane & 7) + ((lane >> 4) & 1) * 8) * 80
                                 + ((lane >> 3) & 1) * 16);

    float acc[2][2][4][4] = {};   // [kind][im][nt][c]

    #pragma unroll
    for (int s = 0; s < 2; s++) {
        int k0 = s * 32;
        unsigned so = sbase + s * G_STG;
        #pragma unroll
        for (int i = 0; i < 2; i++) cpa(so + aoff[i], aptr[i] + k0, asz[i]);
        #pragma unroll
        for (int i = 0; i < 2; i++) cpa(so + boff[i], bptr[i] + k0, 16);
        CP_COMMIT;
    }

    const int NK = HH / 32;
    int s = 0;
    for (int kt = 0; kt < NK; kt++) {
        CP_WAIT1;
        __syncthreads();
        if (kt + 2 < NK) {
            int k0 = (kt + 2) * 32;
            int s2 = s + 2; if (s2 >= 3) s2 -= 3;
            unsigned so = sbase + s2 * G_STG;
            #pragma unroll
            for (int i = 0; i < 2; i++) cpa(so + aoff[i], aptr[i] + k0, asz[i]);
            #pragma unroll
            for (int i = 0; i < 2; i++) cpa(so + boff[i], bptr[i] + k0, 16);
        }
        CP_COMMIT;

        unsigned sA = sbase + s * G_STG + a_lane;
        unsigned sB = sbase + s * G_STG + G_AB + b_lane;
        #pragma unroll
        for (int ks = 0; ks < 2; ks++) {
            unsigned a[2][4];
            #pragma unroll
            for (int im = 0; im < 2; im++)
                ldsm4(a[im], sA + (unsigned)((wm + im * 16) * 80 + ks * 32));
            #pragma unroll
            for (int kind = 0; kind < 2; kind++) {
                #pragma unroll
                for (int ntp = 0; ntp < 2; ntp++) {
                    unsigned b[4];
                    ldsm4(b, sB + (unsigned)((kind * 64 + wn + ntp * 16) * 80 + ks * 32));
                    #pragma unroll
                    for (int im = 0; im < 2; im++) {
                        mma16(acc[kind][im][2 * ntp],     a[im], b[0], b[1]);
                        mma16(acc[kind][im][2 * ntp + 1], a[im], b[2], b[3]);
                    }
                }
            }
        }
        if (++s >= 3) s -= 3;
    }

    #pragma unroll
    for (int im = 0; im < 2; im++) {
        #pragma unroll
        for (int h2 = 0; h2 < 2; h2++) {
            int m = m0 + wm + im * 16 + gq + h2 * 8;
            if (m < cnt) {
                __half* dst = g_h + ((size_t)e * CC + m) * II + n0 + wn + 2 * t;
                #pragma unroll
                for (int nt = 0; nt < 4; nt++) {
                    float g0 = acc[0][im][nt][h2 * 2],     g1 = acc[0][im][nt][h2 * 2 + 1];
                    float u0 = acc[1][im][nt][h2 * 2],     u1 = acc[1][im][nt][h2 * 2 + 1];
                    float r0 = g0 * (1.f / (1.f + expf(-g0))) * u0;
                    float r1 = g1 * (1.f / (1.f + expf(-g1))) * u1;
                    *(__half2*)(dst + nt * 8) = __floats2half2_rn(r0, r1);
                }
            }
        }
    }
}

__global__ __launch_bounds__(256, 2) void gemm2_kernel()
{
    extern __shared__ char smem[];
    int e   = blockIdx.z;
    int cnt = min(g_cnt[e], CC);
    int m0  = blockIdx.y * 128;
    if (m0 >= cnt) return;
    int n0  = blockIdx.x * 128;

    int tid = threadIdx.x;
    unsigned sbase = (unsigned)__cvta_generic_to_shared(smem);

    const __half* aptr[2]; unsigned aoff[2];
    #pragma unroll
    for (int i = 0; i < 2; i++) {
        int c = tid + i * 256;
        int r = c >> 2, ck = c & 3;
        aptr[i] = g_h + ((size_t)e * CC + m0 + r) * II + ck * 8;  // stale rows masked in epilogue
        aoff[i] = (unsigned)(r * 80 + ck * 16);
    }
    const __half* bptr[2]; unsigned boff[2];
    #pragma unroll
    for (int i = 0; i < 2; i++) {
        int c = tid + i * 256;
        int r = c >> 2, ck = c & 3;
        bptr[i] = g_wdh + ((size_t)e * HH + n0 + r) * II + ck * 8;
        boff[i] = (unsigned)(G_AB + r * 80 + ck * 16);
    }

    int warp = tid >> 5, lane = tid & 31;
    int wm = (warp & 3) * 32, wn = (warp >> 2) * 64;
    int gq = lane >> 2, t = lane & 3;

    unsigned a_lane = (unsigned)((lane & 15) * 80 + (lane >> 4) * 16);
    unsigned b_lane = (unsigned)(((lane & 7) + ((lane >> 4) & 1) * 8) * 80
                                 + ((lane >> 3) & 1) * 16);

    float acc[2][8][4] = {};   // [im][nt][c]

    #pragma unroll
    for (int s = 0; s < 2; s++) {
        int k0 = s * 32;
        unsigned so = sbase + s * G_STG;
        #pragma unroll
        for (int i = 0; i < 2; i++) cpa(so + aoff[i], aptr[i] + k0, 16);
        #pragma unroll
        for (int i = 0; i < 2; i++) cpa(so + boff[i], bptr[i] + k0, 16);
        CP_COMMIT;
    }

    const int NK = II / 32;
    int s = 0;
    for (int kt = 0; kt < NK; kt++) {
        CP_WAIT1;
        __syncthreads();
        if (kt + 2 < NK) {
            int k0 = (kt + 2) * 32;
            int s2 = s + 2; if (s2 >= 3) s2 -= 3;
            unsigned so = sbase + s2 * G_STG;
            #pragma unroll
            for (int i = 0; i < 2; i++) cpa(so + aoff[i], aptr[i] + k0, 16);
            #pragma unroll
            for (int i = 0; i < 2; i++) cpa(so + boff[i], bptr[i] + k0, 16);
        }
        CP_COMMIT;

        unsigned sA = sbase + s * G_STG + a_lane;
        unsigned sB = sbase + s * G_STG + G_AB + b_lane;
        #pragma unroll
        for (int ks = 0; ks < 2; ks++) {
            unsigned a[2][4];
            #pragma unroll
            for (int im = 0; im < 2; im++)
                ldsm4(a[im], sA + (unsigned)((wm + im * 16) * 80 + ks * 32));
            #pragma unroll
            for (int ntp = 0; ntp < 4; ntp++) {
                unsigned b[4];
                ldsm4(b, sB + (unsigned)((wn + ntp * 16) * 80 + ks * 32));
                #pragma unroll
                for (int im = 0; im < 2; im++) {
                    mma16(acc[im][2 * ntp],     a[im], b[0], b[1]);
                    mma16(acc[im][2 * ntp + 1], a[im], b[2], b[3]);
                }
            }
        }
        if (++s >= 3) s -= 3;
    }

    #pragma unroll
    for (int im = 0; im < 2; im++) {
        #pragma unroll
        for (int h2 = 0; h2 < 2; h2++) {
            int m = m0 + wm + im * 16 + gq + h2 * 8;
            if (m < cnt) {
                __half* dst = g_y + ((size_t)e * CC + m) * HH + n0 + wn + 2 * t;
                #pragma unroll
                for (int nt = 0; nt < 8; nt++)
                    *(__half2*)(dst + nt * 8) =
                        __floats2half2_rn(acc[im][nt][h2 * 2], acc[im][nt][h2 * 2 + 1]);
            }
        }
    }
}

// ---------------------------------------------------------------------------
// Combine: out[tok] = sum_k w[k] * g_y[e_k, pos_k]  (block per token,
// uint2 = 4-half vector loads)
// ---------------------------------------------------------------------------
__global__ __launch_bounds__(128) void combine_kernel(float* __restrict__ out)
{
    int tok = blockIdx.x;
    int tid = threadIdx.x;

    __shared__ const __half* srow[KK];
    __shared__ float swk[KK];
    if (tid < KK) {
        int e = g_te[tok * KK + tid];
        int p = g_tpos[tok * KK + tid];
        srow[tid] = (p < CC) ? (g_y + ((size_t)e * CC + p) * HH) : (const __half*)0;
        swk[tid]  = g_tw[tok * KK + tid];
    }
    __syncthreads();

    const __half* r[KK]; float w[KK];
    #pragma unroll
    for (int k = 0; k < KK; k++) { r[k] = srow[k]; w[k] = swk[k]; }

    #pragma unroll
    for (int j = 0; j < HH / 4 / 128; j++) {
        int c = tid + j * 128;          // uint2 (4-half) index
        float4 acc = make_float4(0.f, 0.f, 0.f, 0.f);
        #pragma unroll
        for (int k = 0; k < KK; k++) {
            if (r[k]) {
                uint2 hv = *(const uint2*)(r[k] + 4 * c);
                float2 v0 = __half22float2(*(__half2*)&hv.x);
                float2 v1 = __half22float2(*(__half2*)&hv.y);
                acc.x = fmaf(w[k], v0.x, acc.x);
                acc.y = fmaf(w[k], v0.y, acc.y);
                acc.z = fmaf(w[k], v1.x, acc.z);
                acc.w = fmaf(w[k], v1.y, acc.w);
            }
        }
        *(float4*)(out + (size_t)tok * HH + 4 * c) = acc;
    }
}

// ---------------------------------------------------------------------------
extern "C" void kernel_launch(void* const* d_in, const int* in_sizes, int n_in,
                              void* d_out, int out_size)
{
    const float* x      = (const float*)d_in[0];
    const float* gw     = (const float*)d_in[1];
    const float* bias   = (const float*)d_in[2];
    const float* w_gate = (const float*)d_in[3];
    const float* w_up   = (const float*)d_in[4];
    const float* w_down = (const float*)d_in[5];
    float* out = (float*)d_out;

    cudaFuncSetAttribute(gemm1_kernel, cudaFuncAttributeMaxDynamicSharedMemorySize, 3 * G_STG);
    cudaFuncSetAttribute(gemm2_kernel, cudaFuncAttributeMaxDynamicSharedMemorySize, 3 * G_STG);

    zero_cnt_kernel<<<1, 64>>>();
    k1_kernel<<<64 + NC1, 256>>>(x, gw, (const float4*)w_gate, (const float4*)w_up, bias);
    gemm1_kernel<<<dim3(II / 64, CC / 128, EE + 4), 256, 3 * G_STG>>>((const float4*)w_down);
    gemm2_kernel<<<dim3(HH / 128, CC / 128, EE), 256, 3 * G_STG>>>();
    combine_kernel<<<TT, 128>>>(out);
}

// round 15
// speedup vs baseline: 1.4849x; 1.4849x over previous
#include <cuda_runtime.h>
#include <cuda_fp16.h>
#include <math.h>

#define TT 4096
#define HH 1536
#define II 768
#define EE 64
#define KK 8
#define CC 1024

// Scratch (no allocation allowed).
__device__ int    g_cnt[EE];
__device__ int    g_rowtok[EE * CC];
__device__ int    g_te[TT * KK];
__device__ int    g_tpos[TT * KK];
__device__ float  g_tw[TT * KK];
__device__ float  g_logits[(size_t)TT * EE];
__device__ __half g_xh[(size_t)TT * HH];            // fp16 hidden_states
__device__ __half g_h[(size_t)EE * CC * II];        // SwiGLU activations fp16
__device__ __half g_y[(size_t)EE * CC * HH];        // expert outputs fp16
__device__ __half g_wgh[(size_t)EE * II * HH];      // fp16 w_gate
__device__ __half g_wuh[(size_t)EE * II * HH];      // fp16 w_up
__device__ __half g_wdh[(size_t)EE * HH * II];      // fp16 w_down

// ---------------------------------------------------------------------------
// helpers
// ---------------------------------------------------------------------------
__device__ __forceinline__ void mma16(float* c, const unsigned* a, unsigned b0, unsigned b1) {
    asm volatile(
        "mma.sync.aligned.m16n8k16.row.col.f32.f16.f16.f32 "
        "{%0,%1,%2,%3}, {%4,%5,%6,%7}, {%8,%9}, {%0,%1,%2,%3};\n"
        : "+f"(c[0]), "+f"(c[1]), "+f"(c[2]), "+f"(c[3])
        : "r"(a[0]), "r"(a[1]), "r"(a[2]), "r"(a[3]), "r"(b0), "r"(b1));
}
__device__ __forceinline__ void ldsm4(unsigned* r, unsigned addr) {
    asm volatile("ldmatrix.sync.aligned.m8n8.x4.shared.b16 {%0,%1,%2,%3}, [%4];"
                 : "=r"(r[0]), "=r"(r[1]), "=r"(r[2]), "=r"(r[3]) : "r"(addr));
}
__device__ __forceinline__ void cpa(unsigned dst, const void* src, unsigned sz) {
    asm volatile("cp.async.cg.shared.global [%0], [%1], 16, %2;\n"
                 :: "r"(dst), "l"(src), "r"(sz));
}
#define CP_COMMIT asm volatile("cp.async.commit_group;\n")
#define CP_WAIT1  asm volatile("cp.async.wait_group 1;\n")

__device__ __forceinline__ void conv8(const float4* __restrict__ src, uint4* __restrict__ dst,
                                      size_t i) {
    float4 v0 = src[2 * i], v1 = src[2 * i + 1];
    __half2 h0 = __floats2half2_rn(v0.x, v0.y);
    __half2 h1 = __floats2half2_rn(v0.z, v0.w);
    __half2 h2 = __floats2half2_rn(v1.x, v1.y);
    __half2 h3 = __floats2half2_rn(v1.z, v1.w);
    uint4 o;
    o.x = *(unsigned*)&h0; o.y = *(unsigned*)&h1;
    o.z = *(unsigned*)&h2; o.w = *(unsigned*)&h3;
    dst[i] = o;
}

// ---------------------------------------------------------------------------
// K1: fused [logits (blocks 0..63)] + [fp16 conversion of x, w_gate, w_up] +
// cnt zeroing. (R10 exact — low static smem, converter occupancy preserved.)
// ---------------------------------------------------------------------------
#define NC1 1536

__global__ __launch_bounds__(256) void k1_kernel(
    const float* __restrict__ x,
    const float* __restrict__ gw,
    const float4* __restrict__ wg32,
    const float4* __restrict__ wu32)
{
    int bx  = blockIdx.x;
    int tid = threadIdx.x;

    if (bx >= 64) {
        const size_t XCH = (size_t)TT * HH / 8;
        const size_t WCH = (size_t)EE * II * HH / 8;
        const size_t total = XCH + 2 * WCH;
        size_t idx = (size_t)(bx - 64) * 256 + tid;
        for (size_t i = idx; i < total; i += (size_t)NC1 * 256) {
            if (i < XCH)            conv8((const float4*)x, (uint4*)g_xh, i);
            else if (i < XCH + WCH) conv8(wg32, (uint4*)g_wgh, i - XCH);
            else                    conv8(wu32, (uint4*)g_wuh, i - XCH - WCH);
        }
        return;
    }

    if (bx == 0 && tid < EE) g_cnt[tid] = 0;

    __shared__ float As[16][64];
    __shared__ float Bs[16][64];

    int tok0 = bx * 64;
    int lrow = tid >> 2;
    int lkq  = (tid & 3) << 2;
    const float* ap = x  + (size_t)(tok0 + lrow) * HH + lkq;
    const float* bp = gw + (size_t)lrow * HH + lkq;
    int tx = (tid & 15) << 2;
    int ty = (tid >> 4) << 2;
    float acc[4][4] = {};

    for (int k0 = 0; k0 < HH; k0 += 16) {
        float4 av = *(const float4*)(ap + k0);
        float4 bv = *(const float4*)(bp + k0);
        __syncthreads();
        As[lkq][lrow] = av.x; As[lkq + 1][lrow] = av.y; As[lkq + 2][lrow] = av.z; As[lkq + 3][lrow] = av.w;
        Bs[lkq][lrow] = bv.x; Bs[lkq + 1][lrow] = bv.y; Bs[lkq + 2][lrow] = bv.z; Bs[lkq + 3][lrow] = bv.w;
        __syncthreads();
        #pragma unroll
        for (int k = 0; k < 16; k++) {
            float4 a = *(const float4*)&As[k][ty];
            float4 b = *(const float4*)&Bs[k][tx];
            float aa[4] = {a.x, a.y, a.z, a.w};
            float bb[4] = {b.x, b.y, b.z, b.w};
            #pragma unroll
            for (int i = 0; i < 4; i++)
                #pragma unroll
                for (int j = 0; j < 4; j++)
                    acc[i][j] = fmaf(aa[i], bb[j], acc[i][j]);
        }
    }
    #pragma unroll
    for (int i = 0; i < 4; i++)
        #pragma unroll
        for (int j = 0; j < 4; j++)
            g_logits[(size_t)(tok0 + ty + i) * EE + tx + j] = acc[i][j];
}

// ---------------------------------------------------------------------------
// Router part 2: sigmoid + bias + top-8 + atomic dispatch. Warp per token.
// ---------------------------------------------------------------------------
__global__ __launch_bounds__(512) void topk_kernel(const float* __restrict__ bias)
{
    int warp = threadIdx.x >> 5, lane = threadIdx.x & 31;
    int tok  = blockIdx.x * 16 + warp;

    float l0 = g_logits[(size_t)tok * EE + lane];
    float l1 = g_logits[(size_t)tok * EE + lane + 32];
    float sc0 = 1.f / (1.f + expf(-l0));
    float sc1 = 1.f / (1.f + expf(-l1));
    float v0 = sc0 + bias[lane];
    float v1 = sc1 + bias[lane + 32];

    int   my_e = -1;
    float wsum = 0.f;
    #pragma unroll
    for (int k = 0; k < KK; k++) {
        float v; int id;
        if (v0 >= v1) { v = v0; id = lane; } else { v = v1; id = lane + 32; }
        #pragma unroll
        for (int off = 16; off; off >>= 1) {
            float ov = __shfl_xor_sync(0xffffffffu, v, off);
            int   oi = __shfl_xor_sync(0xffffffffu, id, off);
            if (ov > v || (ov == v && oi < id)) { v = ov; id = oi; }
        }
        float s0 = __shfl_sync(0xffffffffu, sc0, id & 31);
        float s1 = __shfl_sync(0xffffffffu, sc1, id & 31);
        wsum += (id < 32) ? s0 : s1;
        if (k == lane) my_e = id;
        if (id == lane)      v0 = -1e30f;
        if (id == lane + 32) v1 = -1e30f;
    }
    {
        int src = (my_e >= 0) ? (my_e & 31) : 0;
        float s0 = __shfl_sync(0xffffffffu, sc0, src);
        float s1 = __shfl_sync(0xffffffffu, sc1, src);
        if (lane < KK) {
            float wgt = ((my_e < 32) ? s0 : s1) / wsum;
            int pos = atomicAdd(&g_cnt[my_e], 1);
            if (pos < CC) g_rowtok[my_e * CC + pos] = tok;
            g_te[tok * KK + lane]   = my_e;
            g_tpos[tok * KK + lane] = pos;
            g_tw[tok * KK + lane]   = wgt;
        }
    }
}

// ---------------------------------------------------------------------------
// GEMM kernels (R10 exact): 256 threads, 8 warps, 2 CTAs/SM. BK=32, 3-stage
// cp.async ring, stage = 20 KB.
// gemm1: BM=128, BN=64 per kind (gate+up), warps 4m x 2n, warp 32 x 32/kind.
// gemm2: BM=128, BN=128, warps 4m x 2n, warp 32 x 64.
// ---------------------------------------------------------------------------
#define G_AB    (128 * 80)
#define G_BB    (128 * 80)
#define G_STG   (G_AB + G_BB)              // 20480 per stage
#define NCD     384

__global__ __launch_bounds__(256, 2) void gemm1_kernel(const float4* __restrict__ wd32)
{
    extern __shared__ char smem[];
    int e   = blockIdx.z;
    int tid = threadIdx.x;

    if (e >= EE) {
        int rank = (e - EE) * 96 + blockIdx.y * 12 + blockIdx.x;
        const size_t WCH = (size_t)EE * HH * II / 8;
        for (size_t i = (size_t)rank * 256 + tid; i < WCH; i += (size_t)NCD * 256)
            conv8(wd32, (uint4*)g_wdh, i);
        return;
    }

    int cnt = min(g_cnt[e], CC);
    int m0  = blockIdx.y * 128;
    if (m0 >= cnt) return;
    int n0  = blockIdx.x * 64;

    unsigned sbase = (unsigned)__cvta_generic_to_shared(smem);

    const __half* aptr[2]; unsigned asz[2]; unsigned aoff[2];
    #pragma unroll
    for (int i = 0; i < 2; i++) {
        int c = tid + i * 256;
        int r = c >> 2, ck = c & 3;
        int m = m0 + r;
        int ok = m < cnt;
        int tok = ok ? g_rowtok[e * CC + m] : 0;
        aptr[i] = g_xh + (size_t)tok * HH + ck * 8;
        asz[i]  = ok ? 16u : 0u;
        aoff[i] = (unsigned)(r * 80 + ck * 16);
    }
    const __half* bptr[2]; unsigned boff[2];
    #pragma unroll
    for (int i = 0; i < 2; i++) {
        int c = tid + i * 256;
        int r = c >> 2, ck = c & 3;
        const __half* base = (r < 64)
            ? g_wgh + ((size_t)e * II + n0 + r) * HH
            : g_wuh + ((size_t)e * II + n0 + (r - 64)) * HH;
        bptr[i] = base + ck * 8;
        boff[i] = (unsigned)(G_AB + r * 80 + ck * 16);
    }

    int warp = tid >> 5, lane = tid & 31;
    int wm = (warp & 3) * 32, wn = (warp >> 2) * 32;
    int gq = lane >> 2, t = lane & 3;

    unsigned a_lane = (unsigned)((lane & 15) * 80 + (lane >> 4) * 16);
    unsigned b_lane = (unsigned)(((lane & 7) + ((lane >> 4) & 1) * 8) * 80
                                 + ((lane >> 3) & 1) * 16);

    float acc[2][2][4][4] = {};   // [kind][im][nt][c]

    #pragma unroll
    for (int s = 0; s < 2; s++) {
        int k0 = s * 32;
        unsigned so = sbase + s * G_STG;
        #pragma unroll
        for (int i = 0; i < 2; i++) cpa(so + aoff[i], aptr[i] + k0, asz[i]);
        #pragma unroll
        for (int i = 0; i < 2; i++) cpa(so + boff[i], bptr[i] + k0, 16);
        CP_COMMIT;
    }

    const int NK = HH / 32;
    int s = 0;
    for (int kt = 0; kt < NK; kt++) {
        CP_WAIT1;
        __syncthreads();
        if (kt + 2 < NK) {
            int k0 = (kt + 2) * 32;
            int s2 = s + 2; if (s2 >= 3) s2 -= 3;
            unsigned so = sbase + s2 * G_STG;
            #pragma unroll
            for (int i = 0; i < 2; i++) cpa(so + aoff[i], aptr[i] + k0, asz[i]);
            #pragma unroll
            for (int i = 0; i < 2; i++) cpa(so + boff[i], bptr[i] + k0, 16);
        }
        CP_COMMIT;

        unsigned sA = sbase + s * G_STG + a_lane;
        unsigned sB = sbase + s * G_STG + G_AB + b_lane;
        #pragma unroll
        for (int ks = 0; ks < 2; ks++) {
            unsigned a[2][4];
            #pragma unroll
            for (int im = 0; im < 2; im++)
                ldsm4(a[im], sA + (unsigned)((wm + im * 16) * 80 + ks * 32));
            #pragma unroll
            for (int kind = 0; kind < 2; kind++) {
                #pragma unroll
                for (int ntp = 0; ntp < 2; ntp++) {
                    unsigned b[4];
                    ldsm4(b, sB + (unsigned)((kind * 64 + wn + ntp * 16) * 80 + ks * 32));
                    #pragma unroll
                    for (int im = 0; im < 2; im++) {
                        mma16(acc[kind][im][2 * ntp],     a[im], b[0], b[1]);
                        mma16(acc[kind][im][2 * ntp + 1], a[im], b[2], b[3]);
                    }
                }
            }
        }
        if (++s >= 3) s -= 3;
    }

    #pragma unroll
    for (int im = 0; im < 2; im++) {
        #pragma unroll
        for (int h2 = 0; h2 < 2; h2++) {
            int m = m0 + wm + im * 16 + gq + h2 * 8;
            if (m < cnt) {
                __half* dst = g_h + ((size_t)e * CC + m) * II + n0 + wn + 2 * t;
                #pragma unroll
                for (int nt = 0; nt < 4; nt++) {
                    float g0 = acc[0][im][nt][h2 * 2],     g1 = acc[0][im][nt][h2 * 2 + 1];
                    float u0 = acc[1][im][nt][h2 * 2],     u1 = acc[1][im][nt][h2 * 2 + 1];
                    float r0 = g0 * (1.f / (1.f + expf(-g0))) * u0;
                    float r1 = g1 * (1.f / (1.f + expf(-g1))) * u1;
                    *(__half2*)(dst + nt * 8) = __floats2half2_rn(r0, r1);
                }
            }
        }
    }
}

__global__ __launch_bounds__(256, 2) void gemm2_kernel()
{
    extern __shared__ char smem[];
    int e   = blockIdx.z;
    int cnt = min(g_cnt[e], CC);
    int m0  = blockIdx.y * 128;
    if (m0 >= cnt) return;
    int n0  = blockIdx.x * 128;

    int tid = threadIdx.x;
    unsigned sbase = (unsigned)__cvta_generic_to_shared(smem);

    const __half* aptr[2]; unsigned aoff[2];
    #pragma unroll
    for (int i = 0; i < 2; i++) {
        int c = tid + i * 256;
        int r = c >> 2, ck = c & 3;
        aptr[i] = g_h + ((size_t)e * CC + m0 + r) * II + ck * 8;  // stale rows masked in epilogue
        aoff[i] = (unsigned)(r * 80 + ck * 16);
    }
    const __half* bptr[2]; unsigned boff[2];
    #pragma unroll
    for (int i = 0; i < 2; i++) {
        int c = tid + i * 256;
        int r = c >> 2, ck = c & 3;
        bptr[i] = g_wdh + ((size_t)e * HH + n0 + r) * II + ck * 8;
        boff[i] = (unsigned)(G_AB + r * 80 + ck * 16);
    }

    int warp = tid >> 5, lane = tid & 31;
    int wm = (warp & 3) * 32, wn = (warp >> 2) * 64;
    int gq = lane >> 2, t = lane & 3;

    unsigned a_lane = (unsigned)((lane & 15) * 80 + (lane >> 4) * 16);
    unsigned b_lane = (unsigned)(((lane & 7) + ((lane >> 4) & 1) * 8) * 80
                                 + ((lane >> 3) & 1) * 16);

    float acc[2][8][4] = {};   // [im][nt][c]

    #pragma unroll
    for (int s = 0; s < 2; s++) {
        int k0 = s * 32;
        unsigned so = sbase + s * G_STG;
        #pragma unroll
        for (int i = 0; i < 2; i++) cpa(so + aoff[i], aptr[i] + k0, 16);
        #pragma unroll
        for (int i = 0; i < 2; i++) cpa(so + boff[i], bptr[i] + k0, 16);
        CP_COMMIT;
    }

    const int NK = II / 32;
    int s = 0;
    for (int kt = 0; kt < NK; kt++) {
        CP_WAIT1;
        __syncthreads();
        if (kt + 2 < NK) {
            int k0 = (kt + 2) * 32;
            int s2 = s + 2; if (s2 >= 3) s2 -= 3;
            unsigned so = sbase + s2 * G_STG;
            #pragma unroll
            for (int i = 0; i < 2; i++) cpa(so + aoff[i], aptr[i] + k0, 16);
            #pragma unroll
            for (int i = 0; i < 2; i++) cpa(so + boff[i], bptr[i] + k0, 16);
        }
        CP_COMMIT;

        unsigned sA = sbase + s * G_STG + a_lane;
        unsigned sB = sbase + s * G_STG + G_AB + b_lane;
        #pragma unroll
        for (int ks = 0; ks < 2; ks++) {
            unsigned a[2][4];
            #pragma unroll
            for (int im = 0; im < 2; im++)
                ldsm4(a[im], sA + (unsigned)((wm + im * 16) * 80 + ks * 32));
            #pragma unroll
            for (int ntp = 0; ntp < 4; ntp++) {
                unsigned b[4];
                ldsm4(b, sB + (unsigned)((wn + ntp * 16) * 80 + ks * 32));
                #pragma unroll
                for (int im = 0; im < 2; im++) {
                    mma16(acc[im][2 * ntp],     a[im], b[0], b[1]);
                    mma16(acc[im][2 * ntp + 1], a[im], b[2], b[3]);
                }
            }
        }
        if (++s >= 3) s -= 3;
    }

    #pragma unroll
    for (int im = 0; im < 2; im++) {
        #pragma unroll
        for (int h2 = 0; h2 < 2; h2++) {
            int m = m0 + wm + im * 16 + gq + h2 * 8;
            if (m < cnt) {
                __half* dst = g_y + ((size_t)e * CC + m) * HH + n0 + wn + 2 * t;
                #pragma unroll
                for (int nt = 0; nt < 8; nt++)
                    *(__half2*)(dst + nt * 8) =
                        __floats2half2_rn(acc[im][nt][h2 * 2], acc[im][nt][h2 * 2 + 1]);
            }
        }
    }
}

// ---------------------------------------------------------------------------
// Combine: out[tok] = sum_k w[k] * g_y[e_k, pos_k]  (block per token,
// uint2 = 4-half vector loads)
// ---------------------------------------------------------------------------
__global__ __launch_bounds__(128) void combine_kernel(float* __restrict__ out)
{
    int tok = blockIdx.x;
    int tid = threadIdx.x;

    __shared__ const __half* srow[KK];
    __shared__ float swk[KK];
    if (tid < KK) {
        int e = g_te[tok * KK + tid];
        int p = g_tpos[tok * KK + tid];
        srow[tid] = (p < CC) ? (g_y + ((size_t)e * CC + p) * HH) : (const __half*)0;
        swk[tid]  = g_tw[tok * KK + tid];
    }
    __syncthreads();

    const __half* r[KK]; float w[KK];
    #pragma unroll
    for (int k = 0; k < KK; k++) { r[k] = srow[k]; w[k] = swk[k]; }

    #pragma unroll
    for (int j = 0; j < HH / 4 / 128; j++) {
        int c = tid + j * 128;          // uint2 (4-half) index
        float4 acc = make_float4(0.f, 0.f, 0.f, 0.f);
        #pragma unroll
        for (int k = 0; k < KK; k++) {
            if (r[k]) {
                uint2 hv = *(const uint2*)(r[k] + 4 * c);
                float2 v0 = __half22float2(*(__half2*)&hv.x);
                float2 v1 = __half22float2(*(__half2*)&hv.y);
                acc.x = fmaf(w[k], v0.x, acc.x);
                acc.y = fmaf(w[k], v0.y, acc.y);
                acc.z = fmaf(w[k], v1.x, acc.z);
                acc.w = fmaf(w[k], v1.y, acc.w);
            }
        }
        *(float4*)(out + (size_t)tok * HH + 4 * c) = acc;
    }
}

// ---------------------------------------------------------------------------
extern "C" void kernel_launch(void* const* d_in, const int* in_sizes, int n_in,
                              void* d_out, int out_size)
{
    const float* x      = (const float*)d_in[0];
    const float* gw     = (const float*)d_in[1];
    const float* bias   = (const float*)d_in[2];
    const float* w_gate = (const float*)d_in[3];
    const float* w_up   = (const float*)d_in[4];
    const float* w_down = (const float*)d_in[5];
    float* out = (float*)d_out;

    cudaFuncSetAttribute(gemm1_kernel, cudaFuncAttributeMaxDynamicSharedMemorySize, 3 * G_STG);
    cudaFuncSetAttribute(gemm2_kernel, cudaFuncAttributeMaxDynamicSharedMemorySize, 3 * G_STG);

    k1_kernel<<<64 + NC1, 256>>>(x, gw, (const float4*)w_gate, (const float4*)w_up);
    topk_kernel<<<TT / 16, 512>>>(bias);
    gemm1_kernel<<<dim3(II / 64, CC / 128, EE + 4), 256, 3 * G_STG>>>((const float4*)w_down);
    gemm2_kernel<<<dim3(HH / 128, CC / 128, EE), 256, 3 * G_STG>>>();
    combine_kernel<<<TT, 128>>>(out);
}

// round 16
// speedup vs baseline: 1.5851x; 1.0675x over previous
#include <cuda_runtime.h>
#include <cuda_fp16.h>
#include <math.h>

#define TT 4096
#define HH 1536
#define II 768
#define EE 64
#define KK 8
#define CC 1024

// Scratch (no allocation allowed).
__device__ int    g_cnt[EE];
__device__ int    g_rowtok[EE * CC];
__device__ int    g_te[TT * KK];
__device__ int    g_tpos[TT * KK];
__device__ float  g_tw[TT * KK];
__device__ float  g_logits[(size_t)TT * EE];
__device__ __half g_xh[(size_t)TT * HH];            // fp16 hidden_states
__device__ __half g_h[(size_t)EE * CC * II];        // SwiGLU activations fp16
__device__ __half g_y[(size_t)EE * CC * HH];        // expert outputs fp16
__device__ __half g_wgh[(size_t)EE * II * HH];      // fp16 w_gate
__device__ __half g_wuh[(size_t)EE * II * HH];      // fp16 w_up
__device__ __half g_wdh[(size_t)EE * HH * II];      // fp16 w_down

// ---------------------------------------------------------------------------
// helpers
// ---------------------------------------------------------------------------
__device__ __forceinline__ void mma16(float* c, const unsigned* a, unsigned b0, unsigned b1) {
    asm volatile(
        "mma.sync.aligned.m16n8k16.row.col.f32.f16.f16.f32 "
        "{%0,%1,%2,%3}, {%4,%5,%6,%7}, {%8,%9}, {%0,%1,%2,%3};\n"
        : "+f"(c[0]), "+f"(c[1]), "+f"(c[2]), "+f"(c[3])
        : "r"(a[0]), "r"(a[1]), "r"(a[2]), "r"(a[3]), "r"(b0), "r"(b1));
}
__device__ __forceinline__ void ldsm4(unsigned* r, unsigned addr) {
    asm volatile("ldmatrix.sync.aligned.m8n8.x4.shared.b16 {%0,%1,%2,%3}, [%4];"
                 : "=r"(r[0]), "=r"(r[1]), "=r"(r[2]), "=r"(r[3]) : "r"(addr));
}
__device__ __forceinline__ void cpa(unsigned dst, const void* src, unsigned sz) {
    asm volatile("cp.async.cg.shared.global [%0], [%1], 16, %2;\n"
                 :: "r"(dst), "l"(src), "r"(sz));
}
#define CP_COMMIT asm volatile("cp.async.commit_group;\n")
#define CP_WAIT1  asm volatile("cp.async.wait_group 1;\n")

__device__ __forceinline__ void conv8(const float4* __restrict__ src, uint4* __restrict__ dst,
                                      size_t i) {
    float4 v0 = src[2 * i], v1 = src[2 * i + 1];
    __half2 h0 = __floats2half2_rn(v0.x, v0.y);
    __half2 h1 = __floats2half2_rn(v0.z, v0.w);
    __half2 h2 = __floats2half2_rn(v1.x, v1.y);
    __half2 h3 = __floats2half2_rn(v1.z, v1.w);
    uint4 o;
    o.x = *(unsigned*)&h0; o.y = *(unsigned*)&h1;
    o.z = *(unsigned*)&h2; o.w = *(unsigned*)&h3;
    dst[i] = o;
}

// ---------------------------------------------------------------------------
// K1: fused [logits (blocks 0..63)] + [fp16 conversion of x, w_gate, w_up] +
// cnt zeroing.
// ---------------------------------------------------------------------------
#define NC1 1536

__global__ __launch_bounds__(256) void k1_kernel(
    const float* __restrict__ x,
    const float* __restrict__ gw,
    const float4* __restrict__ wg32,
    const float4* __restrict__ wu32)
{
    int bx  = blockIdx.x;
    int tid = threadIdx.x;

    if (bx >= 64) {
        const size_t XCH = (size_t)TT * HH / 8;
        const size_t WCH = (size_t)EE * II * HH / 8;
        const size_t total = XCH + 2 * WCH;
        size_t idx = (size_t)(bx - 64) * 256 + tid;
        for (size_t i = idx; i < total; i += (size_t)NC1 * 256) {
            if (i < XCH)            conv8((const float4*)x, (uint4*)g_xh, i);
            else if (i < XCH + WCH) conv8(wg32, (uint4*)g_wgh, i - XCH);
            else                    conv8(wu32, (uint4*)g_wuh, i - XCH - WCH);
        }
        return;
    }

    if (bx == 0 && tid < EE) g_cnt[tid] = 0;

    __shared__ float As[16][64];
    __shared__ float Bs[16][64];

    int tok0 = bx * 64;
    int lrow = tid >> 2;
    int lkq  = (tid & 3) << 2;
    const float* ap = x  + (size_t)(tok0 + lrow) * HH + lkq;
    const float* bp = gw + (size_t)lrow * HH + lkq;
    int tx = (tid & 15) << 2;
    int ty = (tid >> 4) << 2;
    float acc[4][4] = {};

    for (int k0 = 0; k0 < HH; k0 += 16) {
        float4 av = *(const float4*)(ap + k0);
        float4 bv = *(const float4*)(bp + k0);
        __syncthreads();
        As[lkq][lrow] = av.x; As[lkq + 1][lrow] = av.y; As[lkq + 2][lrow] = av.z; As[lkq + 3][lrow] = av.w;
        Bs[lkq][lrow] = bv.x; Bs[lkq + 1][lrow] = bv.y; Bs[lkq + 2][lrow] = bv.z; Bs[lkq + 3][lrow] = bv.w;
        __syncthreads();
        #pragma unroll
        for (int k = 0; k < 16; k++) {
            float4 a = *(const float4*)&As[k][ty];
            float4 b = *(const float4*)&Bs[k][tx];
            float aa[4] = {a.x, a.y, a.z, a.w};
            float bb[4] = {b.x, b.y, b.z, b.w};
            #pragma unroll
            for (int i = 0; i < 4; i++)
                #pragma unroll
                for (int j = 0; j < 4; j++)
                    acc[i][j] = fmaf(aa[i], bb[j], acc[i][j]);
        }
    }
    #pragma unroll
    for (int i = 0; i < 4; i++)
        #pragma unroll
        for (int j = 0; j < 4; j++)
            g_logits[(size_t)(tok0 + ty + i) * EE + tx + j] = acc[i][j];
}

// ---------------------------------------------------------------------------
// Router part 2: sigmoid + bias + top-8 + atomic dispatch. Warp per token.
// Exact expf here: routing selection is tie-sensitive.
// ---------------------------------------------------------------------------
__global__ __launch_bounds__(512) void topk_kernel(const float* __restrict__ bias)
{
    int warp = threadIdx.x >> 5, lane = threadIdx.x & 31;
    int tok  = blockIdx.x * 16 + warp;

    float l0 = g_logits[(size_t)tok * EE + lane];
    float l1 = g_logits[(size_t)tok * EE + lane + 32];
    float sc0 = 1.f / (1.f + expf(-l0));
    float sc1 = 1.f / (1.f + expf(-l1));
    float v0 = sc0 + bias[lane];
    float v1 = sc1 + bias[lane + 32];

    int   my_e = -1;
    float wsum = 0.f;
    #pragma unroll
    for (int k = 0; k < KK; k++) {
        float v; int id;
        if (v0 >= v1) { v = v0; id = lane; } else { v = v1; id = lane + 32; }
        #pragma unroll
        for (int off = 16; off; off >>= 1) {
            float ov = __shfl_xor_sync(0xffffffffu, v, off);
            int   oi = __shfl_xor_sync(0xffffffffu, id, off);
            if (ov > v || (ov == v && oi < id)) { v = ov; id = oi; }
        }
        float s0 = __shfl_sync(0xffffffffu, sc0, id & 31);
        float s1 = __shfl_sync(0xffffffffu, sc1, id & 31);
        wsum += (id < 32) ? s0 : s1;
        if (k == lane) my_e = id;
        if (id == lane)      v0 = -1e30f;
        if (id == lane + 32) v1 = -1e30f;
    }
    {
        int src = (my_e >= 0) ? (my_e & 31) : 0;
        float s0 = __shfl_sync(0xffffffffu, sc0, src);
        float s1 = __shfl_sync(0xffffffffu, sc1, src);
        if (lane < KK) {
            float wgt = ((my_e < 32) ? s0 : s1) / wsum;
            int pos = atomicAdd(&g_cnt[my_e], 1);
            if (pos < CC) g_rowtok[my_e * CC + pos] = tok;
            g_te[tok * KK + lane]   = my_e;
            g_tpos[tok * KK + lane] = pos;
            g_tw[tok * KK + lane]   = wgt;
        }
    }
}

// ---------------------------------------------------------------------------
// GEMM kernels: R10 geometry (256 threads, 8 warps, 2 CTAs/SM, BK=32,
// 3-stage cp.async ring). Change vs R15: prefetch cp.async is issued AFTER
// the ks=0 ldsm/mma group so post-barrier ldsm gets LSU priority.
// ---------------------------------------------------------------------------
#define G_AB    (128 * 80)
#define G_BB    (128 * 80)
#define G_STG   (G_AB + G_BB)              // 20480 per stage
#define NCD     384

__global__ __launch_bounds__(256, 2) void gemm1_kernel(const float4* __restrict__ wd32)
{
    extern __shared__ char smem[];
    int e   = blockIdx.z;
    int tid = threadIdx.x;

    if (e >= EE) {
        int rank = (e - EE) * 96 + blockIdx.y * 12 + blockIdx.x;
        const size_t WCH = (size_t)EE * HH * II / 8;
        for (size_t i = (size_t)rank * 256 + tid; i < WCH; i += (size_t)NCD * 256)
            conv8(wd32, (uint4*)g_wdh, i);
        return;
    }

    int cnt = min(g_cnt[e], CC);
    int m0  = blockIdx.y * 128;
    if (m0 >= cnt) return;
    int n0  = blockIdx.x * 64;

    unsigned sbase = (unsigned)__cvta_generic_to_shared(smem);

    const __half* aptr[2]; unsigned asz[2]; unsigned aoff[2];
    #pragma unroll
    for (int i = 0; i < 2; i++) {
        int c = tid + i * 256;
        int r = c >> 2, ck = c & 3;
        int m = m0 + r;
        int ok = m < cnt;
        int tok = ok ? g_rowtok[e * CC + m] : 0;
        aptr[i] = g_xh + (size_t)tok * HH + ck * 8;
        asz[i]  = ok ? 16u : 0u;
        aoff[i] = (unsigned)(r * 80 + ck * 16);
    }
    const __half* bptr[2]; unsigned boff[2];
    #pragma unroll
    for (int i = 0; i < 2; i++) {
        int c = tid + i * 256;
        int r = c >> 2, ck = c & 3;
        const __half* base = (r < 64)
            ? g_wgh + ((size_t)e * II + n0 + r) * HH
            : g_wuh + ((size_t)e * II + n0 + (r - 64)) * HH;
        bptr[i] = base + ck * 8;
        boff[i] = (unsigned)(G_AB + r * 80 + ck * 16);
    }

    int warp = tid >> 5, lane = tid & 31;
    int wm = (warp & 3) * 32, wn = (warp >> 2) * 32;
    int gq = lane >> 2, t = lane & 3;

    unsigned a_lane = (unsigned)((lane & 15) * 80 + (lane >> 4) * 16);
    unsigned b_lane = (unsigned)(((lane & 7) + ((lane >> 4) & 1) * 8) * 80
                                 + ((lane >> 3) & 1) * 16);

    float acc[2][2][4][4] = {};   // [kind][im][nt][c]

    #pragma unroll
    for (int s = 0; s < 2; s++) {
        int k0 = s * 32;
        unsigned so = sbase + s * G_STG;
        #pragma unroll
        for (int i = 0; i < 2; i++) cpa(so + aoff[i], aptr[i] + k0, asz[i]);
        #pragma unroll
        for (int i = 0; i < 2; i++) cpa(so + boff[i], bptr[i] + k0, 16);
        CP_COMMIT;
    }

    const int NK = HH / 32;
    int s = 0;
    for (int kt = 0; kt < NK; kt++) {
        CP_WAIT1;
        __syncthreads();
        unsigned sA = sbase + s * G_STG + a_lane;
        unsigned sB = sbase + s * G_STG + G_AB + b_lane;

        // ks = 0: fragments first (LSU priority for the blocking loads)
        {
            unsigned a[2][4];
            #pragma unroll
            for (int im = 0; im < 2; im++)
                ldsm4(a[im], sA + (unsigned)((wm + im * 16) * 80));
            #pragma unroll
            for (int kind = 0; kind < 2; kind++) {
                #pragma unroll
                for (int ntp = 0; ntp < 2; ntp++) {
                    unsigned b[4];
                    ldsm4(b, sB + (unsigned)((kind * 64 + wn + ntp * 16) * 80));
                    #pragma unroll
                    for (int im = 0; im < 2; im++) {
                        mma16(acc[kind][im][2 * ntp],     a[im], b[0], b[1]);
                        mma16(acc[kind][im][2 * ntp + 1], a[im], b[2], b[3]);
                    }
                }
            }
        }
        // prefetch kt+2 (needed two iterations out; yields LSU to ldsm above)
        if (kt + 2 < NK) {
            int k0 = (kt + 2) * 32;
            int s2 = s + 2; if (s2 >= 3) s2 -= 3;
            unsigned so = sbase + s2 * G_STG;
            #pragma unroll
            for (int i = 0; i < 2; i++) cpa(so + aoff[i], aptr[i] + k0, asz[i]);
            #pragma unroll
            for (int i = 0; i < 2; i++) cpa(so + boff[i], bptr[i] + k0, 16);
        }
        CP_COMMIT;
        // ks = 1
        {
            unsigned a[2][4];
            #pragma unroll
            for (int im = 0; im < 2; im++)
                ldsm4(a[im], sA + (unsigned)((wm + im * 16) * 80 + 32));
            #pragma unroll
            for (int kind = 0; kind < 2; kind++) {
                #pragma unroll
                for (int ntp = 0; ntp < 2; ntp++) {
                    unsigned b[4];
                    ldsm4(b, sB + (unsigned)((kind * 64 + wn + ntp * 16) * 80 + 32));
                    #pragma unroll
                    for (int im = 0; im < 2; im++) {
                        mma16(acc[kind][im][2 * ntp],     a[im], b[0], b[1]);
                        mma16(acc[kind][im][2 * ntp + 1], a[im], b[2], b[3]);
                    }
                }
            }
        }
        if (++s >= 3) s -= 3;
    }

    #pragma unroll
    for (int im = 0; im < 2; im++) {
        #pragma unroll
        for (int h2 = 0; h2 < 2; h2++) {
            int m = m0 + wm + im * 16 + gq + h2 * 8;
            if (m < cnt) {
                __half* dst = g_h + ((size_t)e * CC + m) * II + n0 + wn + 2 * t;
                #pragma unroll
                for (int nt = 0; nt < 4; nt++) {
                    float g0 = acc[0][im][nt][h2 * 2],     g1 = acc[0][im][nt][h2 * 2 + 1];
                    float u0 = acc[1][im][nt][h2 * 2],     u1 = acc[1][im][nt][h2 * 2 + 1];
                    float r0 = g0 * (1.f / (1.f + __expf(-g0))) * u0;
                    float r1 = g1 * (1.f / (1.f + __expf(-g1))) * u1;
                    *(__half2*)(dst + nt * 8) = __floats2half2_rn(r0, r1);
                }
            }
        }
    }
}

__global__ __launch_bounds__(256, 2) void gemm2_kernel()
{
    extern __shared__ char smem[];
    int e   = blockIdx.z;
    int cnt = min(g_cnt[e], CC);
    int m0  = blockIdx.y * 128;
    if (m0 >= cnt) return;
    int n0  = blockIdx.x * 128;

    int tid = threadIdx.x;
    unsigned sbase = (unsigned)__cvta_generic_to_shared(smem);

    const __half* aptr[2]; unsigned aoff[2];
    #pragma unroll
    for (int i = 0; i < 2; i++) {
        int c = tid + i * 256;
        int r = c >> 2, ck = c & 3;
        aptr[i] = g_h + ((size_t)e * CC + m0 + r) * II + ck * 8;  // stale rows masked in epilogue
        aoff[i] = (unsigned)(r * 80 + ck * 16);
    }
    const __half* bptr[2]; unsigned boff[2];
    #pragma unroll
    for (int i = 0; i < 2; i++) {
        int c = tid + i * 256;
        int r = c >> 2, ck = c & 3;
        bptr[i] = g_wdh + ((size_t)e * HH + n0 + r) * II + ck * 8;
        boff[i] = (unsigned)(G_AB + r * 80 + ck * 16);
    }

    int warp = tid >> 5, lane = tid & 31;
    int wm = (warp & 3) * 32, wn = (warp >> 2) * 64;
    int gq = lane >> 2, t = lane & 3;

    unsigned a_lane = (unsigned)((lane & 15) * 80 + (lane >> 4) * 16);
    unsigned b_lane = (unsigned)(((lane & 7) + ((lane >> 4) & 1) * 8) * 80
                                 + ((lane >> 3) & 1) * 16);

    float acc[2][8][4] = {};   // [im][nt][c]

    #pragma unroll
    for (int s = 0; s < 2; s++) {
        int k0 = s * 32;
        unsigned so = sbase + s * G_STG;
        #pragma unroll
        for (int i = 0; i < 2; i++) cpa(so + aoff[i], aptr[i] + k0, 16);
        #pragma unroll
        for (int i = 0; i < 2; i++) cpa(so + boff[i], bptr[i] + k0, 16);
        CP_COMMIT;
    }

    const int NK = II / 32;
    int s = 0;
    for (int kt = 0; kt < NK; kt++) {
        CP_WAIT1;
        __syncthreads();
        unsigned sA = sbase + s * G_STG + a_lane;
        unsigned sB = sbase + s * G_STG + G_AB + b_lane;

        // ks = 0 first (fragment loads get LSU priority)
        {
            unsigned a[2][4];
            #pragma unroll
            for (int im = 0; im < 2; im++)
                ldsm4(a[im], sA + (unsigned)((wm + im * 16) * 80));
            #pragma unroll
            for (int ntp = 0; ntp < 4; ntp++) {
                unsigned b[4];
                ldsm4(b, sB + (unsigned)((wn + ntp * 16) * 80));
                #pragma unroll
                for (int im = 0; im < 2; im++) {
                    mma16(acc[im][2 * ntp],     a[im], b[0], b[1]);
                    mma16(acc[im][2 * ntp + 1], a[im], b[2], b[3]);
                }
            }
        }
        if (kt + 2 < NK) {
            int k0 = (kt + 2) * 32;
            int s2 = s + 2; if (s2 >= 3) s2 -= 3;
            unsigned so = sbase + s2 * G_STG;
            #pragma unroll
            for (int i = 0; i < 2; i++) cpa(so + aoff[i], aptr[i] + k0, 16);
            #pragma unroll
            for (int i = 0; i < 2; i++) cpa(so + boff[i], bptr[i] + k0, 16);
        }
        CP_COMMIT;
        // ks = 1
        {
            unsigned a[2][4];
            #pragma unroll
            for (int im = 0; im < 2; im++)
                ldsm4(a[im], sA + (unsigned)((wm + im * 16) * 80 + 32));
            #pragma unroll
            for (int ntp = 0; ntp < 4; ntp++) {
                unsigned b[4];
                ldsm4(b, sB + (unsigned)((wn + ntp * 16) * 80 + 32));
                #pragma unroll
                for (int im = 0; im < 2; im++) {
                    mma16(acc[im][2 * ntp],     a[im], b[0], b[1]);
                    mma16(acc[im][2 * ntp + 1], a[im], b[2], b[3]);
                }
            }
        }
        if (++s >= 3) s -= 3;
    }

    #pragma unroll
    for (int im = 0; im < 2; im++) {
        #pragma unroll
        for (int h2 = 0; h2 < 2; h2++) {
            int m = m0 + wm + im * 16 + gq + h2 * 8;
            if (m < cnt) {
                __half* dst = g_y + ((size_t)e * CC + m) * HH + n0 + wn + 2 * t;
                #pragma unroll
                for (int nt = 0; nt < 8; nt++)
                    *(__half2*)(dst + nt * 8) =
                        __floats2half2_rn(acc[im][nt][h2 * 2], acc[im][nt][h2 * 2 + 1]);
            }
        }
    }
}

// ---------------------------------------------------------------------------
// Combine: out[tok] = sum_k w[k] * g_y[e_k, pos_k]  (block per token,
// uint2 = 4-half vector loads)
// ---------------------------------------------------------------------------
__global__ __launch_bounds__(128) void combine_kernel(float* __restrict__ out)
{
    int tok = blockIdx.x;
    int tid = threadIdx.x;

    __shared__ const __half* srow[KK];
    __shared__ float swk[KK];
    if (tid < KK) {
        int e = g_te[tok * KK + tid];
        int p = g_tpos[tok * KK + tid];
        srow[tid] = (p < CC) ? (g_y + ((size_t)e * CC + p) * HH) : (const __half*)0;
        swk[tid]  = g_tw[tok * KK + tid];
    }
    __syncthreads();

    const __half* r[KK]; float w[KK];
    #pragma unroll
    for (int k = 0; k < KK; k++) { r[k] = srow[k]; w[k] = swk[k]; }

    #pragma unroll
    for (int j = 0; j < HH / 4 / 128; j++) {
        int c = tid + j * 128;          // uint2 (4-half) index
        float4 acc = make_float4(0.f, 0.f, 0.f, 0.f);
        #pragma unroll
        for (int k = 0; k < KK; k++) {
            if (r[k]) {
                uint2 hv = *(const uint2*)(r[k] + 4 * c);
                float2 v0 = __half22float2(*(__half2*)&hv.x);
                float2 v1 = __half22float2(*(__half2*)&hv.y);
                acc.x = fmaf(w[k], v0.x, acc.x);
                acc.y = fmaf(w[k], v0.y, acc.y);
                acc.z = fmaf(w[k], v1.x, acc.z);
                acc.w = fmaf(w[k], v1.y, acc.w);
            }
        }
        *(float4*)(out + (size_t)tok * HH + 4 * c) = acc;
    }
}

// ---------------------------------------------------------------------------
extern "C" void kernel_launch(void* const* d_in, const int* in_sizes, int n_in,
                              void* d_out, int out_size)
{
    const float* x      = (const float*)d_in[0];
    const float* gw     = (const float*)d_in[1];
    const float* bias   = (const float*)d_in[2];
    const float* w_gate = (const float*)d_in[3];
    const float* w_up   = (const float*)d_in[4];
    const float* w_down = (const float*)d_in[5];
    float* out = (float*)d_out;

    cudaFuncSetAttribute(gemm1_kernel, cudaFuncAttributeMaxDynamicSharedMemorySize, 3 * G_STG);
    cudaFuncSetAttribute(gemm2_kernel, cudaFuncAttributeMaxDynamicSharedMemorySize, 3 * G_STG);

    k1_kernel<<<64 + NC1, 256>>>(x, gw, (const float4*)w_gate, (const float4*)w_up);
    topk_kernel<<<TT / 16, 512>>>(bias);
    gemm1_kernel<<<dim3(II / 64, CC / 128, EE + 4), 256, 3 * G_STG>>>((const float4*)w_down);
    gemm2_kernel<<<dim3(HH / 128, CC / 128, EE), 256, 3 * G_STG>>>();
    combine_kernel<<<TT, 128>>>(out);
}